// round 6
// baseline (speedup 1.0000x reference)
#include <cuda_runtime.h>
#include <math.h>

#define BATCH 64
#define NPTS  1024
#define KCPL  256
#define CH1   64
#define CH2   128
#define CH3   1024
#define CHC   1024
#define BN_EPS 1e-5

// ---------------- scratch (device globals; no runtime allocation) ----------------
__device__ float  dY1[BATCH * CH1 * NPTS];          // 16 MB  pre-BN layer1
__device__ float  dY2[BATCH * CH2 * NPTS];          // 32 MB  pre-BN layer2
__device__ float  dY3[BATCH * CH3 * NPTS];          // 256 MB pre-BN layer3
__device__ float  dCrit[BATCH * CHC * KCPL];        // 64 MB  gathered critical feats (post BN+ReLU)
__device__ float  dYc[BATCH * CHC * KCPL];          // 64 MB  pre-BN Wc stage
__device__ float4 dBN1[CH1];                        // {mean, rsqrt(var+eps), gamma, beta}
__device__ float4 dBN2[CH2];
__device__ float4 dBN3[CH3];
__device__ float4 dBNc[CHC];
__device__ float  dMaxVal[BATCH * CH3];
__device__ int    dMaxIdx[BATCH * CH3];
__device__ int    dIdxSel[BATCH * KCPL];
__device__ float  dGfeat[BATCH * CHC];
__device__ float  dH1[BATCH * 512];
__device__ float  dH2[BATCH * 256];

__device__ __forceinline__ float bn_relu(float y, float4 p) {
    // exact reference order: ((y - mean) * rsqrt) * gamma + beta, then relu
    float z = ((y - p.x) * p.y) * p.z + p.w;
    return z > 0.f ? z : 0.f;
}

// ---------------- layer 1: tiny 3->64 matmul (coalesced xyz staging) ----------------
__global__ void mm1_kernel(const float* __restrict__ x, const float* __restrict__ W1) {
    __shared__ float sW[CH1 * 3];
    __shared__ float sX[256 * 3];     // 256 points x 3 coords, staged coalesced
    int t = threadIdx.x;
    if (t < CH1 * 3) sW[t] = W1[t];
    int b = blockIdx.y;
    // slab of 256 points: 768 floats = 192 float4, coalesced
    const float4* src = (const float4*)(x + ((size_t)b * NPTS + blockIdx.x * 256) * 3);
    if (t < 192) ((float4*)sX)[t] = src[t];
    __syncthreads();
    float x0 = sX[t * 3 + 0], x1 = sX[t * 3 + 1], x2 = sX[t * 3 + 2];
    int n = blockIdx.x * 256 + t;
    float* yp = dY1 + (size_t)b * CH1 * NPTS + n;
    #pragma unroll
    for (int o = 0; o < CH1; o++) {
        float v = sW[o * 3] * x0 + sW[o * 3 + 1] * x1 + sW[o * 3 + 2] * x2;
        yp[(size_t)o * NPTS] = v;
    }
}

// ---------------- deterministic per-channel BN stats ----------------
// Y layout: [batch][C][N]; per-channel count = batch*N. Double accumulators,
// fixed traversal + fixed tree => bitwise deterministic run-to-run.
__global__ void stats_kernel(const float* __restrict__ Y, int batch, int C, int N,
                             const float* __restrict__ g, const float* __restrict__ bb,
                             float4* __restrict__ bnp) {
    int c = blockIdx.x;
    int t = threadIdx.x;
    double s = 0.0, s2 = 0.0;
    for (int b = 0; b < batch; b++) {
        const float4* p = (const float4*)(Y + ((size_t)b * C + c) * N);
        for (int i = t; i < N / 4; i += blockDim.x) {
            float4 v4 = p[i];
            double v;
            v = (double)v4.x; s += v; s2 += v * v;
            v = (double)v4.y; s += v; s2 += v * v;
            v = (double)v4.z; s += v; s2 += v * v;
            v = (double)v4.w; s += v; s2 += v * v;
        }
    }
    __shared__ double sh[256], sh2[256];
    sh[t] = s; sh2[t] = s2;
    __syncthreads();
    for (int off = 128; off > 0; off >>= 1) {
        if (t < off) { sh[t] += sh[t + off]; sh2[t] += sh2[t + off]; }
        __syncthreads();
    }
    if (t == 0) {
        double cnt = (double)batch * (double)N;
        double mean = sh[0] / cnt;
        double var = sh2[0] / cnt - mean * mean;
        double r = 1.0 / sqrt(var + BN_EPS);
        bnp[c] = make_float4((float)mean, (float)r, g[c], bb[c]);
    }
}

// ---------------- batched SGEMM: C[z] = A(MxK) * Bop[z](KxN) ----------------
// AFFINE: B element = relu(BN(Braw)) using per-k bnp. 128x128 tile, 8x8/thread.
// Register-staged double-buffered mainloop: one barrier per k-tile, global
// loads of tile k+1 overlap FFMAs on tile k. min 2 CTAs/SM for latency hiding.
#define BM 128
#define BN 128
#define BKT 16

template <bool AFFINE>
__global__ __launch_bounds__(256, 2) void sgemm_kernel(
    const float* __restrict__ A, const float* __restrict__ Bg,
    float* __restrict__ Cg, const float4* __restrict__ bnp,
    int M, int N, int K) {
    __shared__ float As[2][BKT][BM];
    __shared__ float Bs[2][BKT][BN];
    int t = threadIdx.x;
    int bn0 = blockIdx.x * BN;
    int bm0 = blockIdx.y * BM;
    const float* Bb = Bg + (size_t)blockIdx.z * K * N;
    float* Cb = Cg + (size_t)blockIdx.z * M * N;
    int tx = t & 15, ty = t >> 4;

    // per-thread load coordinates (fixed across tiles)
    int aRow0 = (t) >> 2,        aKq0 = (t) & 3;
    int aRow1 = (t + 256) >> 2,  aKq1 = (t + 256) & 3;
    int bRow0 = (t) >> 5,        bC40 = (t) & 31;
    int bRow1 = (t + 256) >> 5,  bC41 = (t + 256) & 31;

    float acc[8][8];
    #pragma unroll
    for (int i = 0; i < 8; i++)
        #pragma unroll
        for (int j = 0; j < 8; j++) acc[i][j] = 0.f;

    // ---- prologue: load tile 0 into buffer 0 ----
    {
        float4 va0 = *(const float4*)(A + (size_t)(bm0 + aRow0) * K + aKq0 * 4);
        float4 va1 = *(const float4*)(A + (size_t)(bm0 + aRow1) * K + aKq1 * 4);
        As[0][aKq0*4+0][aRow0] = va0.x; As[0][aKq0*4+1][aRow0] = va0.y;
        As[0][aKq0*4+2][aRow0] = va0.z; As[0][aKq0*4+3][aRow0] = va0.w;
        As[0][aKq1*4+0][aRow1] = va1.x; As[0][aKq1*4+1][aRow1] = va1.y;
        As[0][aKq1*4+2][aRow1] = va1.z; As[0][aKq1*4+3][aRow1] = va1.w;
        float4 vb0 = *(const float4*)(Bb + (size_t)bRow0 * N + bn0 + bC40 * 4);
        float4 vb1 = *(const float4*)(Bb + (size_t)bRow1 * N + bn0 + bC41 * 4);
        if (AFFINE) {
            float4 p0 = bnp[bRow0], p1 = bnp[bRow1];
            vb0.x = bn_relu(vb0.x, p0); vb0.y = bn_relu(vb0.y, p0);
            vb0.z = bn_relu(vb0.z, p0); vb0.w = bn_relu(vb0.w, p0);
            vb1.x = bn_relu(vb1.x, p1); vb1.y = bn_relu(vb1.y, p1);
            vb1.z = bn_relu(vb1.z, p1); vb1.w = bn_relu(vb1.w, p1);
        }
        *(float4*)(&Bs[0][bRow0][bC40 * 4]) = vb0;
        *(float4*)(&Bs[0][bRow1][bC41 * 4]) = vb1;
    }
    __syncthreads();

    int buf = 0;
    for (int k0 = 0; k0 < K; k0 += BKT) {
        bool has_next = (k0 + BKT) < K;
        float4 ra0, ra1, rb0, rb1;
        if (has_next) {
            int kn = k0 + BKT;
            ra0 = *(const float4*)(A + (size_t)(bm0 + aRow0) * K + kn + aKq0 * 4);
            ra1 = *(const float4*)(A + (size_t)(bm0 + aRow1) * K + kn + aKq1 * 4);
            rb0 = *(const float4*)(Bb + (size_t)(kn + bRow0) * N + bn0 + bC40 * 4);
            rb1 = *(const float4*)(Bb + (size_t)(kn + bRow1) * N + bn0 + bC41 * 4);
            if (AFFINE) {
                float4 p0 = bnp[kn + bRow0], p1 = bnp[kn + bRow1];
                rb0.x = bn_relu(rb0.x, p0); rb0.y = bn_relu(rb0.y, p0);
                rb0.z = bn_relu(rb0.z, p0); rb0.w = bn_relu(rb0.w, p0);
                rb1.x = bn_relu(rb1.x, p1); rb1.y = bn_relu(rb1.y, p1);
                rb1.z = bn_relu(rb1.z, p1); rb1.w = bn_relu(rb1.w, p1);
            }
        }
        // compute current tile
        #pragma unroll
        for (int kk = 0; kk < BKT; kk++) {
            float a[8], b[8];
            float4 a0 = *(const float4*)(&As[buf][kk][ty * 4]);
            float4 a1 = *(const float4*)(&As[buf][kk][64 + ty * 4]);
            float4 b0 = *(const float4*)(&Bs[buf][kk][tx * 4]);
            float4 b1 = *(const float4*)(&Bs[buf][kk][64 + tx * 4]);
            a[0]=a0.x; a[1]=a0.y; a[2]=a0.z; a[3]=a0.w;
            a[4]=a1.x; a[5]=a1.y; a[6]=a1.z; a[7]=a1.w;
            b[0]=b0.x; b[1]=b0.y; b[2]=b0.z; b[3]=b0.w;
            b[4]=b1.x; b[5]=b1.y; b[6]=b1.z; b[7]=b1.w;
            #pragma unroll
            for (int i = 0; i < 8; i++)
                #pragma unroll
                for (int j = 0; j < 8; j++) acc[i][j] += a[i] * b[j];
        }
        if (has_next) {
            int nb = buf ^ 1;
            As[nb][aKq0*4+0][aRow0] = ra0.x; As[nb][aKq0*4+1][aRow0] = ra0.y;
            As[nb][aKq0*4+2][aRow0] = ra0.z; As[nb][aKq0*4+3][aRow0] = ra0.w;
            As[nb][aKq1*4+0][aRow1] = ra1.x; As[nb][aKq1*4+1][aRow1] = ra1.y;
            As[nb][aKq1*4+2][aRow1] = ra1.z; As[nb][aKq1*4+3][aRow1] = ra1.w;
            *(float4*)(&Bs[nb][bRow0][bC40 * 4]) = rb0;
            *(float4*)(&Bs[nb][bRow1][bC41 * 4]) = rb1;
            __syncthreads();
            buf = nb;
        }
    }
    // epilogue: quadrant mapping rows {ty*4+i, 64+ty*4+i}, cols {tx*4.., 64+tx*4..}
    #pragma unroll
    for (int ih = 0; ih < 2; ih++)
        #pragma unroll
        for (int i = 0; i < 4; i++) {
            int row = bm0 + ih * 64 + ty * 4 + i;
            float* cp = Cb + (size_t)row * N + bn0;
            *(float4*)(cp + tx * 4) =
                make_float4(acc[ih*4+i][0], acc[ih*4+i][1], acc[ih*4+i][2], acc[ih*4+i][3]);
            *(float4*)(cp + 64 + tx * 4) =
                make_float4(acc[ih*4+i][4], acc[ih*4+i][5], acc[ih*4+i][6], acc[ih*4+i][7]);
        }
}

// ---------------- per-channel max + first-argmax over points ----------------
__global__ void argmax_kernel() {
    int gw = (blockIdx.x * blockDim.x + threadIdx.x) >> 5;
    int lane = threadIdx.x & 31;
    int b = gw >> 10, c = gw & 1023;
    const float* row = dY3 + ((size_t)b * CH3 + c) * NPTS;
    float4 p = dBN3[c];
    float best = -1e30f; int bi = 0;
    for (int i = lane; i < NPTS; i += 32) {
        float z = bn_relu(row[i], p);
        if (z > best) { best = z; bi = i; }      // strict > keeps first occurrence
    }
    #pragma unroll
    for (int off = 16; off > 0; off >>= 1) {
        float ov = __shfl_down_sync(0xffffffffu, best, off);
        int oi = __shfl_down_sync(0xffffffffu, bi, off);
        if (ov > best || (ov == best && oi < bi)) { best = ov; bi = oi; }
    }
    if (lane == 0) { dMaxVal[gw] = best; dMaxIdx[gw] = bi; }
}

// ---------------- CPL: scores, stable sort, pack, resize ----------------
__global__ __launch_bounds__(1024) void cpl_kernel() {
    __shared__ float sMaxVal[1024];
    __shared__ int   sMaxIdx[1024];
    __shared__ float sScore[1024];
    __shared__ float sKey[1024];
    __shared__ int   sVal[1024];
    __shared__ int   sScan[1024];
    __shared__ int   sPacked[1024];
    int b = blockIdx.x, t = threadIdx.x;
    sMaxVal[t] = dMaxVal[b * 1024 + t];
    sMaxIdx[t] = dMaxIdx[b * 1024 + t];
    __syncthreads();
    // deterministic scatter-add: each point scans channels in ascending order
    float sc = 0.f;
    for (int c = 0; c < 1024; c++)
        if (sMaxIdx[c] == t) sc += sMaxVal[c];
    sScore[t] = sc;
    sKey[t] = __fadd_rn(-sc, __fmul_rn(1e-7f, (float)t));  // adjusted, no fma
    sVal[t] = t;
    __syncthreads();
    // bitonic sort ascending by (key, idx) == stable argsort
    for (int k = 2; k <= 1024; k <<= 1) {
        for (int j = k >> 1; j > 0; j >>= 1) {
            int ixj = t ^ j;
            if (ixj > t) {
                bool up = ((t & k) == 0);
                float k1 = sKey[t], k2 = sKey[ixj];
                int v1 = sVal[t], v2 = sVal[ixj];
                bool gt = (k1 > k2) || (k1 == k2 && v1 > v2);
                if (gt == up) {
                    sKey[t] = k2; sKey[ixj] = k1;
                    sVal[t] = v2; sVal[ixj] = v1;
                }
            }
            __syncthreads();
        }
    }
    int myidx = sVal[t];
    int contrib = (sScore[myidx] > 0.f) ? 1 : 0;
    sScan[t] = contrib;
    __syncthreads();
    // inclusive scan (Hillis-Steele)
    for (int off = 1; off < 1024; off <<= 1) {
        int v = (t >= off) ? sScan[t - off] : 0;
        __syncthreads();
        sScan[t] += v;
        __syncthreads();
    }
    int m = sScan[1023];
    int dest = contrib ? (sScan[t] - 1) : (m + t - sScan[t]);  // stable partition
    sPacked[dest] = myidx;
    __syncthreads();
    if (t < KCPL) {
        float m_eff = (m > 0) ? (float)m : 1024.f;
        int pos;
        if (m_eff >= 256.f) {
            pos = t;
        } else {
            float lin = __fdiv_rn(__fmul_rn((float)t, m_eff - 1.0f), 255.0f);
            int pr = (int)rintf(lin);                 // round half-to-even
            int hi = (int)(m_eff - 1.0f);
            pos = pr < 0 ? 0 : (pr > hi ? hi : pr);
        }
        dIdxSel[b * KCPL + t] = sPacked[pos];
    }
}

// ---------------- gather critical features (apply BN3+ReLU) ----------------
__global__ void gather_kernel() {
    int c = blockIdx.x, b = blockIdx.y, k = threadIdx.x;   // 256 threads
    int j = dIdxSel[b * KCPL + k];
    float4 p = dBN3[c];
    float y = dY3[((size_t)b * CH3 + c) * NPTS + j];
    dCrit[((size_t)b * CHC + c) * KCPL + k] = bn_relu(y, p);
}

// ---------------- max pool over K with BNc+ReLU ----------------
__global__ void pool_kernel() {
    int gw = (blockIdx.x * blockDim.x + threadIdx.x) >> 5;
    int lane = threadIdx.x & 31;
    int b = gw >> 10, o = gw & 1023;
    const float* row = dYc + ((size_t)b * CHC + o) * KCPL;
    float4 p = dBNc[o];
    float best = -1e30f;
    for (int i = lane; i < KCPL; i += 32)
        best = fmaxf(best, bn_relu(row[i], p));
    #pragma unroll
    for (int off = 16; off > 0; off >>= 1)
        best = fmaxf(best, __shfl_down_sync(0xffffffffu, best, off));
    if (lane == 0) dGfeat[b * CHC + o] = best;
}

// ---------------- FC head: per-output-channel block, BN over batch ----------------
template <int KDIM, bool DO_BN>
__global__ __launch_bounds__(256) void fc_kernel(
    const float* __restrict__ X,     // [64][KDIM]
    const float* __restrict__ W,     // [O][KDIM]
    const float* __restrict__ bias,
    const float* __restrict__ g, const float* __restrict__ bb,
    float* __restrict__ out) {       // [64][O]
    int o = blockIdx.x;
    int O = gridDim.x;
    int t = threadIdx.x;
    int bi = t & 63, q = t >> 6;
    const int chunk = KDIM / 4;      // elements per quarter (multiple of 16)
    const float* w = W + (size_t)o * KDIM + q * chunk;
    const float* xr = X + (size_t)bi * KDIM + q * chunk;
    float ps = 0.f;
    // float4 loads; accumulation order x,y,z,w == previous scalar element order
    #pragma unroll 4
    for (int c = 0; c < chunk / 4; c++) {
        float4 wv = *(const float4*)(w + c * 4);
        float4 xv = *(const float4*)(xr + c * 4);
        ps += wv.x * xv.x;
        ps += wv.y * xv.y;
        ps += wv.z * xv.z;
        ps += wv.w * xv.w;
    }
    __shared__ float part[4][64];
    __shared__ float yv[64];
    __shared__ double red[2];
    part[q][bi] = ps;
    __syncthreads();
    if (t < 64)
        yv[t] = ((part[0][t] + part[1][t]) + part[2][t]) + part[3][t] + bias[o];
    __syncthreads();
    if (DO_BN) {
        if (t == 0) {
            double s = 0.0, s2 = 0.0;
            for (int i = 0; i < 64; i++) { double v = yv[i]; s += v; s2 += v * v; }
            double mean = s / 64.0;
            double var = s2 / 64.0 - mean * mean;
            red[0] = mean; red[1] = 1.0 / sqrt(var + BN_EPS);
        }
        __syncthreads();
        if (t < 64) {
            float mean = (float)red[0], r = (float)red[1];
            float z = ((yv[t] - mean) * r) * g[o] + bb[o];
            out[(size_t)t * O + o] = z > 0.f ? z : 0.f;
        }
    } else {
        if (t < 64) out[(size_t)t * O + o] = yv[t];
    }
}

// ---------------- launch ----------------
extern "C" void kernel_launch(void* const* d_in, const int* in_sizes, int n_in,
                              void* d_out, int out_size) {
    const float* x     = (const float*)d_in[0];
    const float* W1    = (const float*)d_in[1];
    const float* g1    = (const float*)d_in[2];
    const float* b1    = (const float*)d_in[3];
    const float* W2    = (const float*)d_in[4];
    const float* g2    = (const float*)d_in[5];
    const float* b2    = (const float*)d_in[6];
    const float* W3    = (const float*)d_in[7];
    const float* g3    = (const float*)d_in[8];
    const float* b3    = (const float*)d_in[9];
    const float* Wc    = (const float*)d_in[10];
    const float* gc    = (const float*)d_in[11];
    const float* bc    = (const float*)d_in[12];
    const float* fc1_w = (const float*)d_in[13];
    const float* fc1_b = (const float*)d_in[14];
    const float* bn1_g = (const float*)d_in[15];
    const float* bn1_b = (const float*)d_in[16];
    const float* fc2_w = (const float*)d_in[17];
    const float* fc2_b = (const float*)d_in[18];
    const float* bn2_g = (const float*)d_in[19];
    const float* bn2_b = (const float*)d_in[20];
    const float* fc3_w = (const float*)d_in[21];
    const float* fc3_b = (const float*)d_in[22];

    float *pY1, *pY2, *pY3, *pCrit, *pYc, *pGfeat, *pH1, *pH2;
    float4 *pBN1, *pBN2, *pBN3, *pBNc;
    cudaGetSymbolAddress((void**)&pY1, dY1);
    cudaGetSymbolAddress((void**)&pY2, dY2);
    cudaGetSymbolAddress((void**)&pY3, dY3);
    cudaGetSymbolAddress((void**)&pCrit, dCrit);
    cudaGetSymbolAddress((void**)&pYc, dYc);
    cudaGetSymbolAddress((void**)&pGfeat, dGfeat);
    cudaGetSymbolAddress((void**)&pH1, dH1);
    cudaGetSymbolAddress((void**)&pH2, dH2);
    cudaGetSymbolAddress((void**)&pBN1, dBN1);
    cudaGetSymbolAddress((void**)&pBN2, dBN2);
    cudaGetSymbolAddress((void**)&pBN3, dBN3);
    cudaGetSymbolAddress((void**)&pBNc, dBNc);

    // layer 1
    mm1_kernel<<<dim3(NPTS / 256, BATCH), 256>>>(x, W1);
    stats_kernel<<<CH1, 256>>>(pY1, BATCH, CH1, NPTS, g1, b1, pBN1);
    // layer 2: 128 x 1024 x 64 per sample
    sgemm_kernel<true><<<dim3(NPTS / BN, CH2 / BM, BATCH), 256>>>(W2, pY1, pY2, pBN1, CH2, NPTS, CH1);
    stats_kernel<<<CH2, 256>>>(pY2, BATCH, CH2, NPTS, g2, b2, pBN2);
    // layer 3: 1024 x 1024 x 128 per sample
    sgemm_kernel<true><<<dim3(NPTS / BN, CH3 / BM, BATCH), 256>>>(W3, pY2, pY3, pBN2, CH3, NPTS, CH2);
    stats_kernel<<<CH3, 256>>>(pY3, BATCH, CH3, NPTS, g3, b3, pBN3);
    // CPL
    argmax_kernel<<<(BATCH * CH3) / 8, 256>>>();
    cpl_kernel<<<BATCH, 1024>>>();
    gather_kernel<<<dim3(CH3, BATCH), 256>>>();
    // Wc stage: 1024 x 256 x 1024 per sample
    sgemm_kernel<false><<<dim3(KCPL / BN, CHC / BM, BATCH), 256>>>(Wc, pCrit, pYc, nullptr, CHC, KCPL, CHC);
    stats_kernel<<<CHC, 256>>>(pYc, BATCH, CHC, KCPL, gc, bc, pBNc);
    pool_kernel<<<(BATCH * CHC) / 8, 256>>>();
    // head
    fc_kernel<1024, true><<<512, 256>>>(pGfeat, fc1_w, fc1_b, bn1_g, bn1_b, pH1);
    fc_kernel<512, true><<<256, 256>>>(pH1, fc2_w, fc2_b, bn2_g, bn2_b, pH2);
    fc_kernel<256, false><<<40, 256>>>(pH2, fc3_w, fc3_b, nullptr, nullptr, (float*)d_out);
    (void)in_sizes; (void)n_in; (void)out_size;
}